// round 2
// baseline (speedup 1.0000x reference)
#include <cuda_runtime.h>

// GCGRUCell fused kernel.
// Shapes (fixed by problem): B=4096, d_in=64, U=128, N=36, C=192, c_cat=768, ORDER=3.
// One CTA per batch element. Entire cell computed from shared memory:
//   z = [x; h]                      (192 x 36 in smem)
//   G_k = G_{k-1} * adj^T rows      (diffusion ping-pong gA/gB)
//   preact_f/u = sum_k W_{f/u,k} @ G_k   (thread t<128: f row o=t over all 36 n;
//                                         t>=128: u row o=t-128; acc in f32x2 regs)
//   r = sigmoid(f); u = sigmoid(u); z_c = [x; r*h]; rerun diffusion
//   c = tanh(sum_k W_{c,k} @ G'_k); out = u*h + (1-u)*c
// All inner loops use packed fma.rn.f32x2 (2 fp32 FMA per issue slot on sm_100a).

typedef unsigned long long ull;

static constexpr int NT      = 256;
static constexpr int NNODE   = 36;
static constexpr int CIN     = 64;
static constexpr int UNITS   = 128;
static constexpr int CCAT    = 192;   // d_in + units
static constexpr int XFLTS   = CIN * NNODE;    // 2304
static constexpr int HFLTS   = UNITS * NNODE;  // 4608
static constexpr int GFLTS   = CCAT * NNODE;   // 6912
static constexpr int AFLTS   = NNODE * NNODE;  // 1296

// smem layout (floats)
static constexpr int OFF_SH  = 0;                    // h   [128][36]
static constexpr int OFF_SX  = OFF_SH + HFLTS;       // x   [64][36]
static constexpr int OFF_GA  = OFF_SX + XFLTS;       // diffusion buf A [192][36]
static constexpr int OFF_GB  = OFF_GA + GFLTS;       // diffusion buf B [192][36]
static constexpr int OFF_AJ  = OFF_GB + GFLTS;       // adj [36][36] (w-major, natural)
static constexpr int OFF_SU  = OFF_AJ + AFLTS;       // u gate [128][36]
static constexpr int SMEM_FLTS = OFF_SU + HFLTS;     // 26640 floats = 106560 B

__device__ __forceinline__ ull pk2(float x, float y) {
    ull r; asm("mov.b64 %0,{%1,%2};" : "=l"(r) : "f"(x), "f"(y)); return r;
}
__device__ __forceinline__ ull pkdup(float x) {
    ull r; asm("mov.b64 %0,{%1,%1};" : "=l"(r) : "f"(x)); return r;
}
__device__ __forceinline__ float2 upk(ull v) {
    float2 r; asm("mov.b64 {%0,%1},%2;" : "=f"(r.x), "=f"(r.y) : "l"(v)); return r;
}
__device__ __forceinline__ void fma2(ull& a, ull x, ull y) {
    asm("fma.rn.f32x2 %0,%1,%2,%0;" : "+l"(a) : "l"(x), "l"(y));
}
__device__ __forceinline__ ull d2u(double d) { return __double_as_longlong(d); }

__device__ __forceinline__ float sigmoidf_(float x) { return 1.f / (1.f + __expf(-x)); }
__device__ __forceinline__ float tanhf_(float x)    { return 2.f / (1.f + __expf(-2.f * x)) - 1.f; }

// dst[c][w] = sum_n src[c][n] * adj[w][n]; all 256 threads, 1728 tasks of 4 c-rows.
// Within a warp: w consecutive -> adj float4 loads tile the 32 banks conflict-free
// (stride 36 floats => start bank 4w+n, 4-wide); src row loads are warp broadcasts.
__device__ __forceinline__ void diffuse(const float* __restrict__ src,
                                        float* __restrict__ dst,
                                        const float* __restrict__ adjS, int t) {
    for (int idx = t; idx < 48 * 36; idx += NT) {
        int w = idx % 36;
        int c = (idx / 36) << 2;
        ull a0 = 0, a1 = 0, a2 = 0, a3 = 0;   // bit pattern 0 == {0.f, 0.f}
        const double2* ar = (const double2*)(adjS + w * 36);
        const double2* s0 = (const double2*)(src + c * 36);
        const double2* s1 = (const double2*)(src + c * 36 + 36);
        const double2* s2 = (const double2*)(src + c * 36 + 72);
        const double2* s3 = (const double2*)(src + c * 36 + 108);
#pragma unroll
        for (int q = 0; q < 9; ++q) {
            double2 ad = ar[q];
            ull aL = d2u(ad.x), aH = d2u(ad.y);
            double2 v;
            v = s0[q]; fma2(a0, d2u(v.x), aL); fma2(a0, d2u(v.y), aH);
            v = s1[q]; fma2(a1, d2u(v.x), aL); fma2(a1, d2u(v.y), aH);
            v = s2[q]; fma2(a2, d2u(v.x), aL); fma2(a2, d2u(v.y), aH);
            v = s3[q]; fma2(a3, d2u(v.x), aL); fma2(a3, d2u(v.y), aH);
        }
        float2 f;
        f = upk(a0); dst[(c + 0) * 36 + w] = f.x + f.y;
        f = upk(a1); dst[(c + 1) * 36 + w] = f.x + f.y;
        f = upk(a2); dst[(c + 2) * 36 + w] = f.x + f.y;
        f = upk(a3); dst[(c + 3) * 36 + w] = f.x + f.y;
    }
}

// Accumulate one k-block: acc[q] (f32x2 over n-pairs, starting at n=noff) +=
// sum_{c=0..191} W[c] * g[c][noff + 2q .. +1].  Smem reads are warp broadcasts.
template <int NP>
__device__ __forceinline__ void accum_chunk(ull* acc, const float* __restrict__ wk,
                                            const float* __restrict__ g, int noff) {
    float4 w4 = *(const float4*)(wk);
#pragma unroll 1
    for (int c0 = 0; c0 < 192; c0 += 4) {
        float4 wnext;
        if (c0 + 4 < 192) wnext = *(const float4*)(wk + c0 + 4);
        const float* base = g + c0 * 36 + noff;
        {
            ull wp = pkdup(w4.x);
            const double2* row = (const double2*)(base);
#pragma unroll
            for (int q = 0; q < NP / 2; ++q) {
                double2 d = row[q];
                fma2(acc[2 * q], d2u(d.x), wp);
                fma2(acc[2 * q + 1], d2u(d.y), wp);
            }
        }
        {
            ull wp = pkdup(w4.y);
            const double2* row = (const double2*)(base + 36);
#pragma unroll
            for (int q = 0; q < NP / 2; ++q) {
                double2 d = row[q];
                fma2(acc[2 * q], d2u(d.x), wp);
                fma2(acc[2 * q + 1], d2u(d.y), wp);
            }
        }
        {
            ull wp = pkdup(w4.z);
            const double2* row = (const double2*)(base + 72);
#pragma unroll
            for (int q = 0; q < NP / 2; ++q) {
                double2 d = row[q];
                fma2(acc[2 * q], d2u(d.x), wp);
                fma2(acc[2 * q + 1], d2u(d.y), wp);
            }
        }
        {
            ull wp = pkdup(w4.w);
            const double2* row = (const double2*)(base + 108);
#pragma unroll
            for (int q = 0; q < NP / 2; ++q) {
                double2 d = row[q];
                fma2(acc[2 * q], d2u(d.x), wp);
                fma2(acc[2 * q + 1], d2u(d.y), wp);
            }
        }
        w4 = wnext;
    }
}

__global__ void __launch_bounds__(NT, 2)
gcgru_kernel(const float* __restrict__ x, const float* __restrict__ h,
             const float* __restrict__ adj,
             const float* __restrict__ Wf, const float* __restrict__ bf,
             const float* __restrict__ Wu, const float* __restrict__ bu,
             const float* __restrict__ Wc, const float* __restrict__ bc,
             float* __restrict__ out) {
    extern __shared__ float sm[];
    float* sh   = sm + OFF_SH;
    float* sx   = sm + OFF_SX;
    float* gA   = sm + OFF_GA;
    float* gB   = sm + OFF_GB;
    float* adjS = sm + OFF_AJ;
    float* su   = sm + OFF_SU;

    const int t = threadIdx.x;
    const int b = blockIdx.x;

    // ---- cooperative loads: x -> {sx, gA[0:64)}, h -> {sh, gA[64:192)}, adj -> adjS
    {
        const float4* x4 = (const float4*)(x + (size_t)b * XFLTS);
        float4* sx4 = (float4*)sx;
        float4* gx4 = (float4*)gA;
        for (int i = t; i < XFLTS / 4; i += NT) { float4 v = x4[i]; sx4[i] = v; gx4[i] = v; }
        const float4* h4 = (const float4*)(h + (size_t)b * HFLTS);
        float4* sh4 = (float4*)sh;
        float4* gh4 = (float4*)(gA + XFLTS);
        for (int i = t; i < HFLTS / 4; i += NT) { float4 v = h4[i]; sh4[i] = v; gh4[i] = v; }
        const float4* a4 = (const float4*)adj;
        float4* as4 = (float4*)adjS;
        for (int i = t; i < AFLTS / 4; i += NT) as4[i] = a4[i];
    }
    __syncthreads();

    const int o = t & 127;

    // ---- pass 1: f (t<128) and u (t>=128) gates; thread owns full 36-col row o.
    ull acc[18];
    {
        const float* Wrow = ((t < 128) ? Wf : Wu) + o * 768;
        float bias = (t < 128) ? bf[o] : bu[o];
#pragma unroll
        for (int q = 0; q < 18; ++q) acc[q] = pk2(bias, bias);
#pragma unroll 1
        for (int k = 0; k < 4; ++k) {
            float* cur  = (k & 1) ? gB : gA;
            float* prev = (k & 1) ? gA : gB;
            if (k) { diffuse(prev, cur, adjS, t); __syncthreads(); }
            accum_chunk<18>(acc, Wrow + k * 192, cur, 0);
        }
    }
    __syncthreads();

    // ---- epilogue 1: r = sigmoid(f) -> gA rows 64..191 as r*h; u -> su
    if (t < 128) {
        float* zrow = gA + (CIN + o) * 36;
        const float* hrow = sh + o * 36;
#pragma unroll
        for (int q = 0; q < 18; ++q) {
            float2 p = upk(acc[q]);
            float2 hv = *(const float2*)(hrow + 2 * q);
            float2 st;
            st.x = sigmoidf_(p.x) * hv.x;
            st.y = sigmoidf_(p.y) * hv.y;
            *(float2*)(zrow + 2 * q) = st;
        }
    } else {
        float* urow = su + o * 36;
#pragma unroll
        for (int q = 0; q < 18; ++q) {
            float2 p = upk(acc[q]);
            float2 st;
            st.x = sigmoidf_(p.x);
            st.y = sigmoidf_(p.y);
            *(float2*)(urow + 2 * q) = st;
        }
    }
    // restore x into gA rows 0..63 (z_c = [x; r*h])
    {
        float4* gx4 = (float4*)gA;
        const float4* sx4 = (const float4*)sx;
        for (int i = t; i < XFLTS / 4; i += NT) gx4[i] = sx4[i];
    }
    __syncthreads();

    // ---- pass 2: c gate. Row o split across two threads: t<128 -> n[0,20), t>=128 -> n[20,36).
    const int noff = (t < 128) ? 0 : 20;
    ull acc2[10];
    {
        const float* Wrow = Wc + o * 768;
        float bias = bc[o];
#pragma unroll
        for (int q = 0; q < 10; ++q) acc2[q] = pk2(bias, bias);
#pragma unroll 1
        for (int k = 0; k < 4; ++k) {
            float* cur  = (k & 1) ? gB : gA;
            float* prev = (k & 1) ? gA : gB;
            if (k) { diffuse(prev, cur, adjS, t); __syncthreads(); }
            if (t < 128) accum_chunk<10>(acc2, Wrow + k * 192, cur, 0);
            else         accum_chunk<8>(acc2, Wrow + k * 192, cur, 20);
        }
    }

    // ---- final combine: out = u*h + (1-u)*c = u*(h-c) + c
    {
        const float* urow = su + o * 36 + noff;
        const float* hrow = sh + o * 36 + noff;
        float* orow = out + ((size_t)b * UNITS + o) * 36 + noff;
        if (t < 128) {
#pragma unroll
            for (int q = 0; q < 10; ++q) {
                float2 p = upk(acc2[q]);
                float cx = tanhf_(p.x), cy = tanhf_(p.y);
                float2 uv = *(const float2*)(urow + 2 * q);
                float2 hv = *(const float2*)(hrow + 2 * q);
                float2 ov;
                ov.x = uv.x * (hv.x - cx) + cx;
                ov.y = uv.y * (hv.y - cy) + cy;
                *(float2*)(orow + 2 * q) = ov;
            }
        } else {
#pragma unroll
            for (int q = 0; q < 8; ++q) {
                float2 p = upk(acc2[q]);
                float cx = tanhf_(p.x), cy = tanhf_(p.y);
                float2 uv = *(const float2*)(urow + 2 * q);
                float2 hv = *(const float2*)(hrow + 2 * q);
                float2 ov;
                ov.x = uv.x * (hv.x - cx) + cx;
                ov.y = uv.y * (hv.y - cy) + cy;
                *(float2*)(orow + 2 * q) = ov;
            }
        }
    }
}

extern "C" void kernel_launch(void* const* d_in, const int* in_sizes, int n_in,
                              void* d_out, int out_size) {
    const float* x   = (const float*)d_in[0];
    const float* h   = (const float*)d_in[1];
    const float* adj = (const float*)d_in[2];
    const float* Wf  = (const float*)d_in[3];
    const float* bf  = (const float*)d_in[4];
    const float* Wu  = (const float*)d_in[5];
    const float* bu  = (const float*)d_in[6];
    const float* Wc  = (const float*)d_in[7];
    const float* bc  = (const float*)d_in[8];
    float* out = (float*)d_out;

    const int B = in_sizes[0] / XFLTS;  // 4096
    const int smem_bytes = SMEM_FLTS * (int)sizeof(float);  // 106560

    // Idempotent, not a stream op: executes immediately (capture-safe).
    cudaFuncSetAttribute(gcgru_kernel, cudaFuncAttributeMaxDynamicSharedMemorySize, smem_bytes);
    gcgru_kernel<<<B, NT, smem_bytes>>>(x, h, adj, Wf, bf, Wu, bu, Wc, bc, out);
}

// round 3
// speedup vs baseline: 1.1252x; 1.1252x over previous
#include <cuda_runtime.h>

// GCGRUCell fused kernel, round 3: register-blocked gate GEMMs (4x12 tiles),
// R=8 diffusion, no sx buffer. B=4096, d_in=64, U=128, N=36, C=192, ORDER=3.
// One CTA per batch element, 256 threads, 2 CTAs/SM.

typedef unsigned long long ull;

static constexpr int NT    = 256;
static constexpr int XFLTS = 64 * 36;    // 2304
static constexpr int HFLTS = 128 * 36;   // 4608
static constexpr int GFLTS = 192 * 36;   // 6912
static constexpr int AFLTS = 36 * 36;    // 1296

// smem layout (floats): sh | gA | gB | adj | su
static constexpr int OFF_SH = 0;
static constexpr int OFF_GA = OFF_SH + HFLTS;          // 4608
static constexpr int OFF_GB = OFF_GA + GFLTS;          // 11520
static constexpr int OFF_AJ = OFF_GB + GFLTS;          // 18432
static constexpr int OFF_SU = OFF_AJ + AFLTS;          // 19728
static constexpr int SMEM_FLTS = OFF_SU + HFLTS;       // 24336 -> 97344 B

__device__ __forceinline__ ull pkdup(float x) {
    ull r; asm("mov.b64 %0,{%1,%1};" : "=l"(r) : "f"(x)); return r;
}
__device__ __forceinline__ float2 upk(ull v) {
    float2 r; asm("mov.b64 {%0,%1},%2;" : "=f"(r.x), "=f"(r.y) : "l"(v)); return r;
}
__device__ __forceinline__ void fma2(ull& a, ull x, ull y) {
    asm("fma.rn.f32x2 %0,%1,%2,%0;" : "+l"(a) : "l"(x), "l"(y));
}
__device__ __forceinline__ void fadd2(ull& a, ull b) {
    asm("add.rn.f32x2 %0,%1,%0;" : "+l"(a) : "l"(b));
}
__device__ __forceinline__ ull d2u(double d) { return __double_as_longlong(d); }

__device__ __forceinline__ float sigmoidf_(float x) { return 1.f / (1.f + __expf(-x)); }
__device__ __forceinline__ float tanhf_(float x)    { return 2.f / (1.f + __expf(-2.f * x)) - 1.f; }

// dst[c][w] = sum_n src[c][n] * adj[w][n]; tasks = 24 c-octets x 36 w.
// Per task: 8 c-rows accumulated vs one adj row (amortizes per-lane adj traffic).
__device__ __forceinline__ void diffuse(const float* __restrict__ src,
                                        float* __restrict__ dst,
                                        const float* __restrict__ adjS, int t) {
    for (int idx = t; idx < 24 * 36; idx += NT) {
        int w  = idx % 36;
        int c8 = (idx / 36) << 3;
        ull a[8];
#pragma unroll
        for (int i = 0; i < 8; ++i) a[i] = 0ull;
        const double2* ar = (const double2*)(adjS + w * 36);
        const double2* s  = (const double2*)(src + c8 * 36);  // row stride = 9 double2
#pragma unroll
        for (int q = 0; q < 9; ++q) {
            double2 ad = ar[q];
            ull aL = d2u(ad.x), aH = d2u(ad.y);
#pragma unroll
            for (int i = 0; i < 8; ++i) {
                double2 v = s[i * 9 + q];
                fma2(a[i], d2u(v.x), aL);
                fma2(a[i], d2u(v.y), aH);
            }
        }
#pragma unroll
        for (int i = 0; i < 8; ++i) {
            float2 f = upk(a[i]);
            dst[(c8 + i) * 36 + w] = f.x + f.y;
        }
    }
}

// 4 output rows x 6 col-pairs tile, one 4-channel reduction step.
// acc[r*6+p] accumulates cols [coff+2p, coff+2p+1]. Per c: 3 LDS.128 : 24 FFMA2.
__device__ __forceinline__ void gate_inner4(ull* __restrict__ acc,
    const float* __restrict__ w0, const float* __restrict__ w1,
    const float* __restrict__ w2, const float* __restrict__ w3,
    const float* __restrict__ g, int coff, int c0) {
    float wa[4][4];
    *(float4*)wa[0] = *(const float4*)(w0 + c0);
    *(float4*)wa[1] = *(const float4*)(w1 + c0);
    *(float4*)wa[2] = *(const float4*)(w2 + c0);
    *(float4*)wa[3] = *(const float4*)(w3 + c0);
#pragma unroll
    for (int j = 0; j < 4; ++j) {
        const double2* row = (const double2*)(g + (c0 + j) * 36 + coff);
        double2 g0 = row[0], g1 = row[1], g2 = row[2];
        ull p0 = d2u(g0.x), p1 = d2u(g0.y), p2 = d2u(g1.x);
        ull p3 = d2u(g1.y), p4 = d2u(g2.x), p5 = d2u(g2.y);
#pragma unroll
        for (int r = 0; r < 4; ++r) {
            ull wp = pkdup(wa[r][j]);
            fma2(acc[r * 6 + 0], p0, wp);
            fma2(acc[r * 6 + 1], p1, wp);
            fma2(acc[r * 6 + 2], p2, wp);
            fma2(acc[r * 6 + 3], p3, wp);
            fma2(acc[r * 6 + 4], p4, wp);
            fma2(acc[r * 6 + 5], p5, wp);
        }
    }
}

__global__ void __launch_bounds__(NT, 2)
gcgru_kernel(const float* __restrict__ x, const float* __restrict__ h,
             const float* __restrict__ adj,
             const float* __restrict__ Wf, const float* __restrict__ bf,
             const float* __restrict__ Wu, const float* __restrict__ bu,
             const float* __restrict__ Wc, const float* __restrict__ bc,
             float* __restrict__ out) {
    extern __shared__ float sm[];
    float* sh   = sm + OFF_SH;
    float* gA   = sm + OFF_GA;
    float* gB   = sm + OFF_GB;
    float* adjS = sm + OFF_AJ;
    float* su   = sm + OFF_SU;

    const int t = threadIdx.x;
    const int b = blockIdx.x;

    // ---- loads: z = [x; h] contiguous into gA; h also into sh; adj into adjS
    const float4* xg = (const float4*)(x + (size_t)b * XFLTS);
    {
        float4* gA4 = (float4*)gA;
        for (int i = t; i < XFLTS / 4; i += NT) gA4[i] = xg[i];
        const float4* hg = (const float4*)(h + (size_t)b * HFLTS);
        float4* gAh4 = (float4*)(gA + XFLTS);
        float4* sh4  = (float4*)sh;
        for (int i = t; i < HFLTS / 4; i += NT) { float4 v = hg[i]; gAh4[i] = v; sh4[i] = v; }
        const float4* a4 = (const float4*)adj;
        float4* as4 = (float4*)adjS;
        for (int i = t; i < AFLTS / 4; i += NT) as4[i] = a4[i];
    }
    __syncthreads();

    // ---- pass 1: f (t<128) and u (t>=128). Thread = 4 rows x col-group.
    // cols computed: [8*cg, 8*cg+12); cols written: cg<3 -> 8, cg==3 -> 12.
    const int  quadRow = (t & ~3) & 127;   // gate-local row base, step 4
    const bool isF     = (t < 128);
    const int  cg      = t & 3;
    const int  coff    = cg * 8;
    ull acc[24];
    {
        const float* Wg = isF ? Wf : Wu;
        const float* bg = isF ? bf : bu;
        const float* wr0 = Wg + (size_t)(quadRow + 0) * 768;
        const float* wr1 = Wg + (size_t)(quadRow + 1) * 768;
        const float* wr2 = Wg + (size_t)(quadRow + 2) * 768;
        const float* wr3 = Wg + (size_t)(quadRow + 3) * 768;
#pragma unroll
        for (int r = 0; r < 4; ++r) {
            ull bp = pkdup(bg[quadRow + r]);
#pragma unroll
            for (int p = 0; p < 6; ++p) acc[r * 6 + p] = bp;
        }
#pragma unroll 1
        for (int k = 0; k < 4; ++k) {
            float* cur  = (k & 1) ? gB : gA;
            float* prev = (k & 1) ? gA : gB;
            if (k) { diffuse(prev, cur, adjS, t); __syncthreads(); }
            const float* w0k = wr0 + k * 192;
            const float* w1k = wr1 + k * 192;
            const float* w2k = wr2 + k * 192;
            const float* w3k = wr3 + k * 192;
#pragma unroll 1
            for (int c0 = 0; c0 < 192; c0 += 4)
                gate_inner4(acc, w0k, w1k, w2k, w3k, cur, coff, c0);
        }
    }
    __syncthreads();

    // ---- epilogue 1: f -> gA rows 64.. as r*h ; u -> su
    {
        const int npw = (cg == 3) ? 6 : 4;
        if (isF) {
#pragma unroll
            for (int r = 0; r < 4; ++r) {
                int row = quadRow + r;
                const float* hrow = sh + row * 36 + coff;
                float* zrow = gA + (64 + row) * 36 + coff;
                for (int p = 0; p < npw; ++p) {
                    float2 v  = upk(acc[r * 6 + p]);
                    float2 hv = *(const float2*)(hrow + 2 * p);
                    float2 s;
                    s.x = sigmoidf_(v.x) * hv.x;
                    s.y = sigmoidf_(v.y) * hv.y;
                    *(float2*)(zrow + 2 * p) = s;
                }
            }
        } else {
#pragma unroll
            for (int r = 0; r < 4; ++r) {
                int row = quadRow + r;
                float* urow = su + row * 36 + coff;
                for (int p = 0; p < npw; ++p) {
                    float2 v = upk(acc[r * 6 + p]);
                    float2 s;
                    s.x = sigmoidf_(v.x);
                    s.y = sigmoidf_(v.y);
                    *(float2*)(urow + 2 * p) = s;
                }
            }
        }
        // restore x into gA rows 0..63 (re-read from global; L2-resident)
        float4* gA4 = (float4*)gA;
        for (int i = t; i < XFLTS / 4; i += NT) gA4[i] = xg[i];
    }
    __syncthreads();

    // ---- pass 2: c gate. Thread = 4 rows x col-group x c-half; shfl-reduce halves.
    const int q2row = (t >> 3) * 4;        // 0..124
    const int cg2   = (t >> 1) & 3;
    const int coff2 = cg2 * 8;
    const int ch    = t & 1;               // c-half: [0,96) or [96,192)
    ull a2[24];
    {
        const float* wr0 = Wc + (size_t)(q2row + 0) * 768;
        const float* wr1 = Wc + (size_t)(q2row + 1) * 768;
        const float* wr2 = Wc + (size_t)(q2row + 2) * 768;
        const float* wr3 = Wc + (size_t)(q2row + 3) * 768;
#pragma unroll
        for (int i = 0; i < 24; ++i) a2[i] = 0ull;
        const int cb = ch * 96;
#pragma unroll 1
        for (int k = 0; k < 4; ++k) {
            float* cur  = (k & 1) ? gB : gA;
            float* prev = (k & 1) ? gA : gB;
            if (k) { diffuse(prev, cur, adjS, t); __syncthreads(); }
            const float* w0k = wr0 + k * 192;
            const float* w1k = wr1 + k * 192;
            const float* w2k = wr2 + k * 192;
            const float* w3k = wr3 + k * 192;
#pragma unroll 1
            for (int c0 = cb; c0 < cb + 96; c0 += 4)
                gate_inner4(a2, w0k, w1k, w2k, w3k, cur, coff2, c0);
        }
    }
    // reduce the two c-halves (partner = lane^1, same rows/cols)
#pragma unroll
    for (int i = 0; i < 24; ++i) {
        ull o = __shfl_xor_sync(0xffffffffu, a2[i], 1);
        fadd2(a2[i], o);
    }

    // ---- final combine: lane ch==0 -> local rows 0,1 ; ch==1 -> rows 2,3
    {
        const int np2 = (cg2 == 3) ? 6 : 4;
#pragma unroll
        for (int rr2 = 0; rr2 < 2; ++rr2) {
            int rl  = 2 * ch + rr2;
            int row = q2row + rl;
            float bb = bc[row];
            const float* urow = su + row * 36 + coff2;
            const float* hrow = sh + row * 36 + coff2;
            float* orow = out + (size_t)b * HFLTS + row * 36 + coff2;
            for (int p = 0; p < np2; ++p) {
                float2 v  = upk(a2[rl * 6 + p]);
                float cx = tanhf_(v.x + bb);
                float cy = tanhf_(v.y + bb);
                float2 uv = *(const float2*)(urow + 2 * p);
                float2 hv = *(const float2*)(hrow + 2 * p);
                float2 ov;
                ov.x = uv.x * (hv.x - cx) + cx;
                ov.y = uv.y * (hv.y - cy) + cy;
                *(float2*)(orow + 2 * p) = ov;
            }
        }
    }
}

extern "C" void kernel_launch(void* const* d_in, const int* in_sizes, int n_in,
                              void* d_out, int out_size) {
    const float* x   = (const float*)d_in[0];
    const float* h   = (const float*)d_in[1];
    const float* adj = (const float*)d_in[2];
    const float* Wf  = (const float*)d_in[3];
    const float* bf  = (const float*)d_in[4];
    const float* Wu  = (const float*)d_in[5];
    const float* bu  = (const float*)d_in[6];
    const float* Wc  = (const float*)d_in[7];
    const float* bc  = (const float*)d_in[8];
    float* out = (float*)d_out;

    const int B = in_sizes[0] / XFLTS;                     // 4096
    const int smem_bytes = SMEM_FLTS * (int)sizeof(float); // 97344

    cudaFuncSetAttribute(gcgru_kernel, cudaFuncAttributeMaxDynamicSharedMemorySize, smem_bytes);
    gcgru_kernel<<<B, NT, smem_bytes>>>(x, h, adj, Wf, bf, Wu, bu, Wc, bc, out);
}